// round 2
// baseline (speedup 1.0000x reference)
#include <cuda_runtime.h>
#include <math.h>

#define SEQ 8192
#define E   384
#define H   192
#define G4  768
#define T   11
#define STARTTAG 9
#define STOPTAG  10
#define NEGV (-10000.0f)
#define CSZ 8   // cluster size per direction

// ---------------- device scratch (static: allowed) ----------------
__device__ float d_gpre[2][SEQ][G4];   // input-projected gates + bias
__device__ float d_h[2][SEQ][H];       // hf, hb
__device__ float d_feats[SEQ][T];

// ---------------- helpers ----------------
__device__ __forceinline__ unsigned smem_u32(const void* p) {
    unsigned a;
    asm("{ .reg .u64 t; cvta.to.shared.u64 t, %1; cvt.u32.u64 %0, t; }"
        : "=r"(a) : "l"(p));
    return a;
}
__device__ __forceinline__ float sigmoidf_(float x) {
    return __fdividef(1.0f, 1.0f + __expf(-x));
}
__device__ __forceinline__ float tanhf_(float x) {
    float ax = fabsf(x);
    float e  = __expf(2.0f * ax);              // may be +inf, handled below
    float r  = 1.0f - __fdividef(2.0f, e + 1.0f);
    return copysignf(r, x);
}

// =====================================================================
// Kernel 1: embedding gather + input projection GEMM (both directions)
// grid (256, 2), 256 threads. Block = 32 timesteps x all 768 gates.
// =====================================================================
__global__ __launch_bounds__(256) void gemm_in_kernel(
    const int* __restrict__ sent, const float* __restrict__ emb,
    const float* __restrict__ w_f, const float* __restrict__ b1f, const float* __restrict__ b2f,
    const float* __restrict__ w_b, const float* __restrict__ b1b, const float* __restrict__ b2b)
{
    __shared__ float xs[E * 32];   // [k][r], 49152 B (exactly 48 KB)
    const int dir = blockIdx.y;
    const int t0  = blockIdx.x * 32;
    const int tid = threadIdx.x;
    const float* w   = dir ? w_b : w_f;
    const float* bb1 = dir ? b1b : b1f;
    const float* bb2 = dir ? b2b : b2f;

    // load X tile: conflict-free STS; gather rows hit L1
    #pragma unroll 1
    for (int i = 0; i < 48; i++) {
        int f = tid + i * 256;
        int r = f & 31, k = f >> 5;
        int tok = __ldg(sent + t0 + r);
        xs[k * 32 + r] = __ldg(emb + (size_t)tok * E + k);
    }
    __syncthreads();

    #pragma unroll 1
    for (int ch = 0; ch < 3; ch++) {
        int g = ch * 256 + tid;
        const float* wr = w + (size_t)g * E;
        float acc[32];
        #pragma unroll
        for (int r = 0; r < 32; r++) acc[r] = 0.0f;

        #pragma unroll 4
        for (int k = 0; k < E; k++) {
            float wv = __ldg(wr + k);
            const float4* x4 = (const float4*)(xs + k * 32);
            #pragma unroll
            for (int q = 0; q < 8; q++) {
                float4 xv = x4[q];            // broadcast across warp
                acc[4*q+0] += xv.x * wv;
                acc[4*q+1] += xv.y * wv;
                acc[4*q+2] += xv.z * wv;
                acc[4*q+3] += xv.w * wv;
            }
        }
        float bias = __ldg(bb1 + g) + __ldg(bb2 + g);
        #pragma unroll
        for (int r = 0; r < 32; r++)
            d_gpre[dir][t0 + r][g] = acc[r] + bias;   // coalesced over g
    }
}

// =====================================================================
// Kernel 2: the two LSTM scans. grid 16 = 2 clusters of 8 CTAs.
// Each CTA owns 24 h-lanes (96 gates: 24 each of i/f/g/o) with its
// W_hh slice (96 fp32/thread) resident in REGISTERS. h broadcast via
// DSMEM stores + cluster barrier each step; h double-buffered by parity.
// =====================================================================
__global__ void __cluster_dims__(CSZ, 1, 1) __launch_bounds__(192, 1)
lstm_kernel(const float* __restrict__ whf, const float* __restrict__ whb)
{
    __shared__ __align__(16) float hbuf[2][H];
    __shared__ float part[192];
    __shared__ float gates[96];

    unsigned rank; asm("mov.u32 %0, %%cluster_ctarank;" : "=r"(rank));
    const int dir = blockIdx.x >> 3;
    const int tid = threadIdx.x;
    const int gl  = tid % 96;          // local gate
    const int kh  = tid / 96;          // k half (0/1)
    const int typ = gl / 24, idx = gl % 24;
    const int gg  = typ * 192 + (int)rank * 24 + idx;   // global gate row
    const float* wh = dir ? whb : whf;

    // resident recurrent weights: 48 packed f32x2 per thread
    unsigned long long wreg[48];
    const unsigned long long* wrow =
        (const unsigned long long*)(wh + (size_t)gg * H) + kh * 48;
    #pragma unroll
    for (int j = 0; j < 48; j++) wreg[j] = __ldg(wrow + j);

    for (int i = tid; i < 2 * H; i += 192) (&hbuf[0][0])[i] = 0.0f;
    float c = 0.0f;                    // cell state lives in tid<24 regs
    __syncthreads();
    asm volatile("barrier.cluster.arrive.aligned;" ::: "memory");
    asm volatile("barrier.cluster.wait.aligned;"   ::: "memory");

    const float* gp = &d_gpre[dir][0][0];
    float* hout = &d_h[dir][0][0];
    const int hidx = (int)rank * 24 + (tid < 24 ? tid : 0);
    unsigned hb_addr[2];
    hb_addr[0] = smem_u32(&hbuf[0][hidx]);
    hb_addr[1] = smem_u32(&hbuf[1][hidx]);

    #pragma unroll 1
    for (int t = 0; t < SEQ; t++) {
        const int s   = dir ? (SEQ - 1 - t) : t;
        const int par = t & 1;

        // prefetch input-projected gate (overlaps the dot below)
        float gpre_v = 0.0f;
        if (tid < 96) gpre_v = __ldg(gp + (size_t)s * G4 + gg);

        // 96-MAC half-dot via packed f32x2 FMA; h broadcast from smem
        const unsigned long long* hs =
            (const unsigned long long*)hbuf[par] + kh * 48;
        unsigned long long acc = 0ull;          // (0.f, 0.f)
        #pragma unroll
        for (int j = 0; j < 48; j++) {
            unsigned long long h2 = hs[j];
            asm("fma.rn.f32x2 %0, %1, %2, %0;" : "+l"(acc) : "l"(h2), "l"(wreg[j]));
        }
        float ax, ay;
        asm("mov.b64 {%0,%1}, %2;" : "=f"(ax), "=f"(ay) : "l"(acc));
        part[tid] = ax + ay;
        __syncthreads();

        if (tid < 96) gates[tid] = part[tid] + part[tid + 96] + gpre_v;
        __syncthreads();

        if (tid < 24) {
            float iv = sigmoidf_(gates[tid]);
            float fv = sigmoidf_(gates[24 + tid]);
            float gv = tanhf_  (gates[48 + tid]);
            float ov = sigmoidf_(gates[72 + tid]);
            c = fv * c + iv * gv;
            float hv = ov * tanhf_(c);
            hout[(size_t)s * H + hidx] = hv;
            // broadcast my h lane to every CTA's next-parity buffer
            unsigned la = hb_addr[par ^ 1];
            unsigned hb = __float_as_uint(hv);
            #pragma unroll
            for (int r = 0; r < CSZ; r++) {
                unsigned ra;
                asm("mapa.shared::cluster.u32 %0, %1, %2;" : "=r"(ra) : "r"(la), "r"(r));
                asm volatile("st.shared::cluster.b32 [%0], %1;" :: "r"(ra), "r"(hb) : "memory");
            }
        }
        // release-arrive orders the DSMEM stores; wait acquires them
        asm volatile("barrier.cluster.arrive.aligned;" ::: "memory");
        asm volatile("barrier.cluster.wait.aligned;"   ::: "memory");
    }
}

// =====================================================================
// Kernel 3: feats[t][tag] = concat(hf,hb)[t] . w_tag[tag] + b_tag
// grid 256, 352 threads (32 timesteps x 11 tags)
// =====================================================================
__global__ __launch_bounds__(352) void feats_kernel(
    const float* __restrict__ wtag, const float* __restrict__ btag)
{
    __shared__ float ws[T * 2 * H];
    __shared__ float bs[T];
    const int tid = threadIdx.x;
    for (int i = tid; i < T * 2 * H; i += 352) ws[i] = __ldg(wtag + i);
    if (tid < T) bs[tid] = __ldg(btag + tid);
    __syncthreads();

    const int tl = tid / T, tag = tid % T;
    const int t = blockIdx.x * 32 + tl;
    float acc = bs[tag];
    const float* wr = ws + tag * (2 * H);
    #pragma unroll 4
    for (int k = 0; k < H; k++) acc += __ldg(&d_h[0][t][k]) * wr[k];
    #pragma unroll 4
    for (int k = 0; k < H; k++) acc += __ldg(&d_h[1][t][k]) * wr[H + k];
    d_feats[t][tag] = acc;
}

// =====================================================================
// Kernel 4: Viterbi forward + backtrace. 1 block, 1 warp.
// v lives in lanes 0..10; backpointers nibble-packed (2/byte) into
// exactly 48 KB static smem so backtrace is LDS-latency.
// =====================================================================
__global__ __launch_bounds__(32) void viterbi_kernel(
    const float* __restrict__ trans, float* __restrict__ out, int out_n)
{
    __shared__ unsigned char bsm[SEQ * 6];   // 49152 B
    const int lane = threadIdx.x;
    const int li = (lane < T) ? lane : 0;

    float tr[T];
    #pragma unroll
    for (int j = 0; j < T; j++) tr[j] = __ldg(trans + li * T + j);
    const float trStop = __ldg(trans + STOPTAG * T + li);

    float v = (lane == STARTTAG) ? 0.0f : NEGV;

    #pragma unroll 1
    for (int t = 0; t < SEQ; t++) {
        float fv = __ldg(&d_feats[t][li]);
        float m = -3.4e38f; int bp = 0;
        #pragma unroll
        for (int j = 0; j < T; j++) {
            float vj = __shfl_sync(0xffffffffu, v, j);
            float sv = vj + tr[j];
            if (sv > m) { m = sv; bp = j; }   // strict > => first argmax
        }
        v = m + fv;
        int pb = __shfl_down_sync(0xffffffffu, bp, 1);
        if (lane < T && !(lane & 1)) {
            unsigned byte = (unsigned)bp | ((lane == 10 ? 0u : (unsigned)pb) << 4);
            bsm[t * 6 + (lane >> 1)] = (unsigned char)byte;
        }
    }

    float term = (lane < T) ? (v + trStop) : -3.4e38f;
    int bidx = lane;
    #pragma unroll
    for (int off = 16; off > 0; off >>= 1) {
        float ov = __shfl_down_sync(0xffffffffu, term, off);
        int   oi = __shfl_down_sync(0xffffffffu, bidx, off);
        if (ov > term || (ov == term && oi < bidx)) { term = ov; bidx = oi; }
    }
    if (lane == 0) {
        if (out_n > 0) out[0] = term;
        int cur = bidx;
        for (int t = SEQ - 1; t >= 0; t--) {
            if (1 + t < out_n) out[1 + t] = (float)cur;
            unsigned char byte = bsm[t * 6 + (cur >> 1)];
            cur = (cur & 1) ? (byte >> 4) : (byte & 15);
        }
    }
}

// =====================================================================
extern "C" void kernel_launch(void* const* d_in, const int* in_sizes, int n_in,
                              void* d_out, int out_size)
{
    const int*   sent   = (const int*)  d_in[0];
    const float* emb    = (const float*)d_in[1];
    const float* w_ih_f = (const float*)d_in[2];
    const float* w_hh_f = (const float*)d_in[3];
    const float* b_ih_f = (const float*)d_in[4];
    const float* b_hh_f = (const float*)d_in[5];
    const float* w_ih_b = (const float*)d_in[6];
    const float* w_hh_b = (const float*)d_in[7];
    const float* b_ih_b = (const float*)d_in[8];
    const float* b_hh_b = (const float*)d_in[9];
    const float* w_tag  = (const float*)d_in[10];
    const float* b_tag  = (const float*)d_in[11];
    const float* trans  = (const float*)d_in[12];
    float* out = (float*)d_out;

    gemm_in_kernel<<<dim3(SEQ / 32, 2), 256>>>(sent, emb,
        w_ih_f, b_ih_f, b_hh_f, w_ih_b, b_ih_b, b_hh_b);
    lstm_kernel<<<2 * CSZ, 192>>>(w_hh_f, w_hh_b);
    feats_kernel<<<SEQ / 32, 352>>>(w_tag, b_tag);
    viterbi_kernel<<<1, 32>>>(trans, out, out_size);
}